// round 2
// baseline (speedup 1.0000x reference)
#include <cuda_runtime.h>
#include <cuda_bf16.h>
#include <cstdint>

// Problem constants
#define B_   128
#define N_   4608
#define IL_  8
#define C_   10
#define L_   16
#define KDIM 160          // C_*L_
#define SROW (B_*KDIM)    // 20480

// Scratch (allocation-free rule: __device__ globals)
__device__ float g_u[(size_t)B_ * N_ * KDIM];   // 377 MB prediction tensor
__device__ float g_b1[(size_t)B_ * N_ * C_];    // routing logits after r=0 update
__device__ float g_s[3][SROW];                  // s accumulators per round
__device__ float g_v[2][SROW];                  // v0, v1

// ---------------------------------------------------------------------------
// Zero the s accumulators (must happen every replay)
// ---------------------------------------------------------------------------
__global__ void k_zero() {
    int i = blockIdx.x * blockDim.x + threadIdx.x;
    if (i < 3 * SROW) ((float*)g_s)[i] = 0.0f;
}

// ---------------------------------------------------------------------------
// K1: u[b,n,k] = sum_j x[b,n,j] * W[n,j,k]
// block = one n, 160 threads (thread = k). W column in registers, x tile in smem.
// ---------------------------------------------------------------------------
__global__ void __launch_bounds__(160) k_compute_u(const float* __restrict__ x,
                                                   const float* __restrict__ W) {
    int n = blockIdx.x;
    int k = threadIdx.x;
    __shared__ float xs[16 * IL_];   // 16 batches of x[b,n,0..7]
    float w[IL_];
    const float* Wn = W + (size_t)n * (IL_ * KDIM);
#pragma unroll
    for (int j = 0; j < IL_; j++) w[j] = Wn[j * KDIM + k];

    for (int b0 = 0; b0 < B_; b0 += 16) {
        __syncthreads();
        if (k < 128) {
            int bl = k >> 3, j = k & 7;
            xs[k] = x[(size_t)(b0 + bl) * (N_ * IL_) + (size_t)n * IL_ + j];
        }
        __syncthreads();
#pragma unroll
        for (int bl = 0; bl < 16; bl++) {
            float4 xa = *(const float4*)&xs[bl * 8];
            float4 xb = *(const float4*)&xs[bl * 8 + 4];
            float acc = fmaf(xa.x, w[0], fmaf(xa.y, w[1], fmaf(xa.z, w[2],
                        fmaf(xa.w, w[3], fmaf(xb.x, w[4], fmaf(xb.y, w[5],
                        fmaf(xb.z, w[6], xb.w * w[7])))))));
            g_u[((size_t)(b0 + bl) * N_ + n) * KDIM + k] = acc;
        }
    }
}

// ---------------------------------------------------------------------------
// K2: s0[b,k] += 0.1 * sum_n u[b,n,k]   (r=0 softmax of zeros = 1/C exactly)
// grid (B_, 18), 256 n per chunk, 160 threads
// ---------------------------------------------------------------------------
__global__ void __launch_bounds__(160) k_s0() {
    int b = blockIdx.x, chunk = blockIdx.y, k = threadIdx.x;
    const float* up = g_u + ((size_t)b * N_ + (size_t)chunk * 256) * KDIM + k;
    float acc = 0.0f;
#pragma unroll 8
    for (int i = 0; i < 256; i++) acc += up[(size_t)i * KDIM];
    atomicAdd(&g_s[0][b * KDIM + k], 0.1f * acc);
}

// ---------------------------------------------------------------------------
// Squash: v = n^2/(1+n^2)/(n+eps) * (s + bias); norm over L=16
// block per b, 160 threads; 16-lane groups are warp-aligned.
// SIN: which s; TO_OUT: write d_out, else g_v[VOUT]
// ---------------------------------------------------------------------------
template <int SIN, int VOUT, bool TO_OUT>
__global__ void __launch_bounds__(160) k_squash(const float* __restrict__ bias,
                                                float* __restrict__ out) {
    int b = blockIdx.x, t = threadIdx.x;
    float val = g_s[SIN][b * KDIM + t] + bias[t];
    float sq = val * val;
    sq += __shfl_xor_sync(0xffffffffu, sq, 8);
    sq += __shfl_xor_sync(0xffffffffu, sq, 4);
    sq += __shfl_xor_sync(0xffffffffu, sq, 2);
    sq += __shfl_xor_sync(0xffffffffu, sq, 1);
    float nrm = sqrtf(sq);
    float f = sq / (1.0f + sq) / (nrm + 1e-7f);
    float res = f * val;
    if (TO_OUT) out[b * KDIM + t] = res;
    else        g_v[VOUT][b * KDIM + t] = res;
}

// ---------------------------------------------------------------------------
// Routing pass.
// Half-warp handles one n: lane c (c<10) owns u[b,n,c,0..15] (4x LDG.128).
//   p[c] = dot16(u, v) (+ b_old for ROUND==2); ROUND==1 writes p as b-logits.
//   softmax over the 10 lanes via 4-shfl butterflies in each 16-lane group.
//   acc[16] accumulates softmax(c)*u over the warp's n range; one atomic set
//   per warp at the end (halves combined first).
// ---------------------------------------------------------------------------
#define NCHUNK 9   // 4608/9 = 512 n per block, 64 per warp
template <int ROUND>
__global__ void __launch_bounds__(256) k_route() {
    int b = blockIdx.x;
    int chunk = blockIdx.y;
    int warp = threadIdx.x >> 5;
    int lane = threadIdx.x & 31;
    int half = lane >> 4;
    int c = lane & 15;
    bool active = (c < C_);

    __shared__ float vs[KDIM];
    const float* v = g_v[ROUND - 1];
    if (threadIdx.x < KDIM) vs[threadIdx.x] = v[b * KDIM + threadIdx.x];
    __syncthreads();

    float vr[L_], acc[L_];
#pragma unroll
    for (int l = 0; l < L_; l++) {
        vr[l] = active ? vs[c * L_ + l] : 0.0f;
        acc[l] = 0.0f;
    }

    const int NPB = N_ / NCHUNK;   // 512
    const int NPW = NPB / 8;       // 64
    int n0 = chunk * NPB + warp * NPW;

    for (int ni = 0; ni < NPW; ni += 2) {
        int n = n0 + ni + half;
        const float* up = g_u + ((size_t)b * N_ + n) * KDIM + c * L_;
        float uvals[L_];
#pragma unroll
        for (int q = 0; q < 4; q++) {
            float4 t4 = active ? *(const float4*)(up + q * 4)
                               : make_float4(0.f, 0.f, 0.f, 0.f);
            uvals[q * 4] = t4.x; uvals[q * 4 + 1] = t4.y;
            uvals[q * 4 + 2] = t4.z; uvals[q * 4 + 3] = t4.w;
        }
        float p = 0.0f;
#pragma unroll
        for (int l = 0; l < L_; l++) p = fmaf(uvals[l], vr[l], p);

        if (ROUND == 2) {
            if (active) p += g_b1[((size_t)b * N_ + n) * C_ + c];
        } else {
            if (active) g_b1[((size_t)b * N_ + n) * C_ + c] = p;
        }

        // softmax over c (10 active lanes per 16-lane group)
        float m = active ? p : -1e30f;
        m = fmaxf(m, __shfl_xor_sync(0xffffffffu, m, 8));
        m = fmaxf(m, __shfl_xor_sync(0xffffffffu, m, 4));
        m = fmaxf(m, __shfl_xor_sync(0xffffffffu, m, 2));
        m = fmaxf(m, __shfl_xor_sync(0xffffffffu, m, 1));
        float e = active ? __expf(p - m) : 0.0f;
        float se = e;
        se += __shfl_xor_sync(0xffffffffu, se, 8);
        se += __shfl_xor_sync(0xffffffffu, se, 4);
        se += __shfl_xor_sync(0xffffffffu, se, 2);
        se += __shfl_xor_sync(0xffffffffu, se, 1);
        float wgt = e / se;
#pragma unroll
        for (int l = 0; l < L_; l++) acc[l] = fmaf(wgt, uvals[l], acc[l]);
    }

    // combine the two half-warps (same c, disjoint n sets)
#pragma unroll
    for (int l = 0; l < L_; l++) acc[l] += __shfl_xor_sync(0xffffffffu, acc[l], 16);
    if (active && half == 0) {
#pragma unroll
        for (int l = 0; l < L_; l++)
            atomicAdd(&g_s[ROUND][b * KDIM + c * L_ + l], acc[l]);
    }
}

// ---------------------------------------------------------------------------
extern "C" void kernel_launch(void* const* d_in, const int* in_sizes, int n_in,
                              void* d_out, int out_size) {
    const float* x    = (const float*)d_in[0];   // [128,12,12,32,8] = [B, N, 8]
    const float* W    = (const float*)d_in[1];   // [4608, 8, 160]
    const float* bias = (const float*)d_in[2];   // [10, 16]
    float* out = (float*)d_out;                  // [128, 10, 16]
    (void)in_sizes; (void)n_in; (void)out_size;

    k_zero<<<(3 * SROW + 255) / 256, 256>>>();
    k_compute_u<<<N_, 160>>>(x, W);
    k_s0<<<dim3(B_, 18), 160>>>();
    k_squash<0, 0, false><<<B_, 160>>>(bias, nullptr);
    k_route<1><<<dim3(B_, NCHUNK), 256>>>();
    k_squash<1, 1, false><<<B_, 160>>>(bias, nullptr);
    k_route<2><<<dim3(B_, NCHUNK), 256>>>();
    k_squash<2, 0, true><<<B_, 160>>>(bias, out);
}

// round 3
// speedup vs baseline: 1.1011x; 1.1011x over previous
#include <cuda_runtime.h>
#include <cuda_fp16.h>
#include <cstdint>

// Problem constants
#define B_   128
#define N_   4608
#define IL_  8
#define C_   10
#define L_   16
#define KDIM 160          // C_*L_
#define SROW (B_*KDIM)    // 20480

// Scratch (allocation-free rule: __device__ globals)
__device__ __half g_uh[(size_t)B_ * N_ * KDIM];   // 188 MB prediction tensor (fp16)
__device__ float  g_s[3][SROW];                   // s accumulators per round

// ---------------------------------------------------------------------------
// Zero the s accumulators (must happen every replay)
// ---------------------------------------------------------------------------
__global__ void k_zero() {
    int i = blockIdx.x * blockDim.x + threadIdx.x;
    if (i < 3 * SROW) ((float*)g_s)[i] = 0.0f;
}

// ---------------------------------------------------------------------------
// K1: u[b,n,k] = sum_j x[b,n,j] * W[n,j,k]  (fp16 store) FUSED with
//     s0[b,k] += 0.1 * sum_n u[b,n,k]   (softmax of zero logits = 1/C exact)
// grid (B/16, N/64), block 160 (thread = k). s0 partials reduced over the
// 64-n tile in registers -> 16 atomics per thread.
// ---------------------------------------------------------------------------
__global__ void __launch_bounds__(160) k_u_s0(const float* __restrict__ x,
                                              const float* __restrict__ W) {
    int b0 = blockIdx.x * 16;
    int n0 = blockIdx.y * 64;
    int k = threadIdx.x;
    __shared__ float xs[16 * 64 * 8];   // 32 KB x tile [bi][nj][j]
    for (int idx = k; idx < 16 * 64 * 8; idx += 160) {
        int bi = idx >> 9, r = idx & 511;   // r = nj*8+j, contiguous in gmem
        xs[idx] = x[(size_t)(b0 + bi) * (N_ * IL_) + (size_t)n0 * IL_ + r];
    }
    __syncthreads();

    float s0acc[16];
#pragma unroll
    for (int i = 0; i < 16; i++) s0acc[i] = 0.0f;

    for (int nj = 0; nj < 64; nj++) {
        const float* Wn = W + (size_t)(n0 + nj) * (IL_ * KDIM);
        float w[IL_];
#pragma unroll
        for (int j = 0; j < IL_; j++) w[j] = Wn[j * KDIM + k];
#pragma unroll
        for (int bi = 0; bi < 16; bi++) {
            const float* xp = &xs[(bi * 64 + nj) * 8];
            float acc = fmaf(xp[0], w[0], 0.f);
#pragma unroll
            for (int j = 1; j < IL_; j++) acc = fmaf(xp[j], w[j], acc);
            g_uh[((size_t)(b0 + bi) * N_ + (n0 + nj)) * KDIM + k] =
                __float2half_rn(acc);
            s0acc[bi] += acc;
        }
    }
#pragma unroll
    for (int bi = 0; bi < 16; bi++)
        atomicAdd(&g_s[0][(b0 + bi) * KDIM + k], 0.1f * s0acc[bi]);
}

// ---------------------------------------------------------------------------
// squash helper applied to one element owned by thread in an aligned 16-group
// ---------------------------------------------------------------------------
__device__ __forceinline__ float squash16(float val) {
    float sq = val * val;
    sq += __shfl_xor_sync(0xffffffffu, sq, 8);
    sq += __shfl_xor_sync(0xffffffffu, sq, 4);
    sq += __shfl_xor_sync(0xffffffffu, sq, 2);
    sq += __shfl_xor_sync(0xffffffffu, sq, 1);
    float nrm = sqrtf(sq);
    return sq / (1.0f + sq) / (nrm + 1e-7f) * val;
}

// ---------------------------------------------------------------------------
// Routing pass (squash fused into the prologue; no b-logit tensor).
// ROUND==1: logit p = u.v0                -> accumulate s1
// ROUND==2: logit p = u.v0 + u.v1 = u.(v0+v1) -> accumulate s2
// Half-warp handles one n; lane c<10 owns u[b,n,c,0:16] (2x LDG.128 fp16).
// ---------------------------------------------------------------------------
#define NCHUNK 9   // 4608/9 = 512 n per block, 64 per warp
template <int ROUND>
__global__ void __launch_bounds__(256) k_route(const float* __restrict__ bias) {
    int b = blockIdx.x;
    int chunk = blockIdx.y;
    int t = threadIdx.x;

    // prologue: v(s0) [+ v(s1)] into smem, summed for the round-2 logit
    __shared__ float vs[KDIM];     // v0  (round1)  or v0+v1 (round2)
    __shared__ float vw[KDIM];     // weighting v for this round (v_{ROUND-1})
    if (t < KDIM) {
        float bval = bias[t];
        float v0 = squash16(g_s[0][b * KDIM + t] + bval);
        if (ROUND == 1) {
            vs[t] = v0;
            vw[t] = v0;
        } else {
            float v1 = squash16(g_s[1][b * KDIM + t] + bval);
            vs[t] = v0 + v1;
            vw[t] = v1;
        }
    }
    __syncthreads();
    (void)vw;

    int warp = t >> 5;
    int lane = t & 31;
    int half = lane >> 4;
    int c = lane & 15;
    bool active = (c < C_);

    float vr[L_], acc[L_];
#pragma unroll
    for (int l = 0; l < L_; l++) {
        vr[l] = active ? vs[c * L_ + l] : 0.0f;
        acc[l] = 0.0f;
    }

    const int NPB = N_ / NCHUNK;   // 512
    const int NPW = NPB / 8;       // 64
    int n0 = chunk * NPB + warp * NPW;

    for (int ni = 0; ni < NPW; ni += 2) {
        int n = n0 + ni + half;
        const __half* up = g_uh + ((size_t)b * N_ + n) * KDIM + c * L_;
        uint4 za = make_uint4(0u, 0u, 0u, 0u), zb = za;
        uint4 ua = active ? *(const uint4*)up : za;
        uint4 ub = active ? *(const uint4*)(up + 8) : zb;
        float f[L_];
        {
            unsigned uu[8] = {ua.x, ua.y, ua.z, ua.w, ub.x, ub.y, ub.z, ub.w};
#pragma unroll
            for (int q = 0; q < 8; q++) {
                float2 fq = __half22float2(*(const __half2*)&uu[q]);
                f[2 * q] = fq.x; f[2 * q + 1] = fq.y;
            }
        }
        float p = 0.0f;
#pragma unroll
        for (int l = 0; l < L_; l++) p = fmaf(f[l], vr[l], p);

        // softmax over c (10 active lanes per 16-lane group)
        float m = active ? p : -1e30f;
        m = fmaxf(m, __shfl_xor_sync(0xffffffffu, m, 8));
        m = fmaxf(m, __shfl_xor_sync(0xffffffffu, m, 4));
        m = fmaxf(m, __shfl_xor_sync(0xffffffffu, m, 2));
        m = fmaxf(m, __shfl_xor_sync(0xffffffffu, m, 1));
        float e = active ? __expf(p - m) : 0.0f;
        float se = e;
        se += __shfl_xor_sync(0xffffffffu, se, 8);
        se += __shfl_xor_sync(0xffffffffu, se, 4);
        se += __shfl_xor_sync(0xffffffffu, se, 2);
        se += __shfl_xor_sync(0xffffffffu, se, 1);
        float wgt = e / se;
#pragma unroll
        for (int l = 0; l < L_; l++) acc[l] = fmaf(wgt, f[l], acc[l]);
    }

    // combine the two half-warps (same c, disjoint n sets)
#pragma unroll
    for (int l = 0; l < L_; l++)
        acc[l] += __shfl_xor_sync(0xffffffffu, acc[l], 16);
    if (active && half == 0) {
#pragma unroll
        for (int l = 0; l < L_; l++)
            atomicAdd(&g_s[ROUND][b * KDIM + c * L_ + l], acc[l]);
    }
}

// ---------------------------------------------------------------------------
// Final squash of s2 -> d_out
// ---------------------------------------------------------------------------
__global__ void __launch_bounds__(160) k_out(const float* __restrict__ bias,
                                             float* __restrict__ out) {
    int b = blockIdx.x, t = threadIdx.x;
    out[b * KDIM + t] = squash16(g_s[2][b * KDIM + t] + bias[t]);
}

// ---------------------------------------------------------------------------
extern "C" void kernel_launch(void* const* d_in, const int* in_sizes, int n_in,
                              void* d_out, int out_size) {
    const float* x    = (const float*)d_in[0];   // [128,12,12,32,8] = [B, N, 8]
    const float* W    = (const float*)d_in[1];   // [4608, 8, 160]
    const float* bias = (const float*)d_in[2];   // [10, 16]
    float* out = (float*)d_out;                  // [128, 10, 16]
    (void)in_sizes; (void)n_in; (void)out_size;

    k_zero<<<(3 * SROW + 255) / 256, 256>>>();
    k_u_s0<<<dim3(B_ / 16, N_ / 64), 160>>>(x, W);
    k_route<1><<<dim3(B_, NCHUNK), 256>>>(bias);
    k_route<2><<<dim3(B_, NCHUNK), 256>>>(bias);
    k_out<<<B_, 160>>>(bias, out);
}

// round 4
// speedup vs baseline: 1.3356x; 1.2129x over previous
#include <cuda_runtime.h>
#include <cuda_fp16.h>
#include <cstdint>

// Problem constants
#define B_   128
#define N_   4608
#define IL_  8
#define C_   10
#define L_   16
#define KDIM 160          // C_*L_
#define SROW (B_*KDIM)    // 20480

// Scratch (allocation-free rule: __device__ globals)
__device__ __half g_uh[(size_t)B_ * N_ * KDIM];   // 188 MB prediction tensor (fp16)
__device__ float  g_s[3][SROW];                   // s accumulators per round

// ---------------------------------------------------------------------------
// Zero the s accumulators (must happen every replay)
// ---------------------------------------------------------------------------
__global__ void k_zero() {
    int i = blockIdx.x * blockDim.x + threadIdx.x;
    if (i < 3 * SROW) ((float*)g_s)[i] = 0.0f;
}

// ---------------------------------------------------------------------------
// K1: u[b,n,k] = sum_j x[b,n,j] * W[n,j,k]  (fp16 store) FUSED with
//     s0[b,k] += 0.1 * sum_n u[b,n,k]
// grid (B/32, N/32), block 160 (thread = k). x tile in smem read via
// LDS.128 broadcast (all lanes same address -> conflict-free).
// ---------------------------------------------------------------------------
__global__ void __launch_bounds__(160) k_u_s0(const float* __restrict__ x,
                                              const float* __restrict__ W) {
    int b0 = blockIdx.x * 32;
    int n0 = blockIdx.y * 32;
    int k = threadIdx.x;
    __shared__ float4 xs[32 * 32 * 2];   // 32 KB  [bi][nj][2]  (8 floats per (bi,nj))
    for (int idx = k; idx < 32 * 32 * 2; idx += 160) {
        int bi = idx >> 6, r = idx & 63;   // r indexes 32n*2 float4 = contiguous 1KB
        xs[idx] = ((const float4*)(x + (size_t)(b0 + bi) * (N_ * IL_)
                                     + (size_t)n0 * IL_))[r];
    }
    __syncthreads();

    float s0acc[32];
#pragma unroll
    for (int i = 0; i < 32; i++) s0acc[i] = 0.0f;

    for (int nj = 0; nj < 32; nj++) {
        const float* Wn = W + (size_t)(n0 + nj) * (IL_ * KDIM);
        float w[IL_];
#pragma unroll
        for (int j = 0; j < IL_; j++) w[j] = Wn[j * KDIM + k];
        __half* op = g_uh + ((size_t)b0 * N_ + (n0 + nj)) * KDIM + k;
#pragma unroll 8
        for (int bi = 0; bi < 32; bi++) {
            float4 xa = xs[(bi * 32 + nj) * 2];
            float4 xb = xs[(bi * 32 + nj) * 2 + 1];
            float acc = fmaf(xa.x, w[0], fmaf(xa.y, w[1], fmaf(xa.z, w[2],
                        fmaf(xa.w, w[3], fmaf(xb.x, w[4], fmaf(xb.y, w[5],
                        fmaf(xb.z, w[6], xb.w * w[7])))))));
            op[(size_t)bi * (N_ * KDIM)] = __float2half_rn(acc);
            s0acc[bi] += acc;
        }
    }
#pragma unroll
    for (int bi = 0; bi < 32; bi++)
        atomicAdd(&g_s[0][(b0 + bi) * KDIM + k], 0.1f * s0acc[bi]);
}

// ---------------------------------------------------------------------------
// squash helper applied to one element owned by thread in an aligned 16-group
// ---------------------------------------------------------------------------
__device__ __forceinline__ float squash16(float val) {
    float sq = val * val;
    sq += __shfl_xor_sync(0xffffffffu, sq, 8);
    sq += __shfl_xor_sync(0xffffffffu, sq, 4);
    sq += __shfl_xor_sync(0xffffffffu, sq, 2);
    sq += __shfl_xor_sync(0xffffffffu, sq, 1);
    float nrm = sqrtf(sq);
    return sq / (1.0f + sq) / (nrm + 1e-7f) * val;
}

// ---------------------------------------------------------------------------
// Routing pass (squash fused into the prologue; no b-logit tensor).
// ROUND==1: logit p = u.v0                 -> accumulate s1
// ROUND==2: logit p = u.(v0+v1)            -> accumulate s2
// 10-lane groups: warp = 3 groups (lanes 0-29), group g owns one n per
// iteration; lane c in [0,10) owns u[b,n,c,0:16] (2x LDG.128 fp16).
// No max-subtraction (logits bounded by ~2). Sum over the 10-lane group via
// 4 predicated shfl.idx steps + 1 broadcast.
// ---------------------------------------------------------------------------
#define FULLM 0xffffffffu
template <int ROUND>
__global__ void __launch_bounds__(256) k_route(const float* __restrict__ bias) {
    int b = blockIdx.x;
    int chunk = blockIdx.y;       // 0..5, 768 n per block
    int t = threadIdx.x;

    __shared__ float vs[KDIM];    // v0 (round1) or v0+v1 (round2)
    if (t < KDIM) {
        float bval = bias[t];
        float v0 = squash16(g_s[0][b * KDIM + t] + bval);
        if (ROUND == 1) vs[t] = v0;
        else            vs[t] = v0 + squash16(g_s[1][b * KDIM + t] + bval);
    }
    __syncthreads();

    int warp = t >> 5;
    int lane = t & 31;
    int g = (lane >= 20) ? 2 : (lane >= 10 ? 1 : 0);
    int c = lane - g * 10;
    bool active = (lane < 30);

    float vr[L_], acc[L_];
#pragma unroll
    for (int l = 0; l < L_; l++) {
        vr[l] = active ? vs[c * L_ + l] : 0.0f;
        acc[l] = 0.0f;
    }

    // warp covers 96 consecutive n: 32 iterations x 3 groups
    int base_n = chunk * 768 + warp * 96;
    const __half* ubase = g_uh + ((size_t)b * N_ + base_n) * KDIM + c * L_;

#pragma unroll 2
    for (int it = 0; it < 32; it++) {
        const __half* up = ubase + (size_t)(it * 3 + g) * KDIM;
        uint4 z4 = make_uint4(0u, 0u, 0u, 0u);
        uint4 ua = active ? *(const uint4*)up : z4;
        uint4 ub = active ? *(const uint4*)(up + 8) : z4;
        float f[L_];
        {
            unsigned uu[8] = {ua.x, ua.y, ua.z, ua.w, ub.x, ub.y, ub.z, ub.w};
#pragma unroll
            for (int q = 0; q < 8; q++) {
                float2 fq = __half22float2(*(const __half2*)&uu[q]);
                f[2 * q] = fq.x; f[2 * q + 1] = fq.y;
            }
        }
        float p = 0.0f;
#pragma unroll
        for (int l = 0; l < L_; l++) p = fmaf(f[l], vr[l], p);

        float e = active ? __expf(p) : 0.0f;

        // sum over the 10-lane group (c = 0..9)
        float s_ = e, tmp;
        tmp = __shfl_sync(FULLM, s_, lane + 8);  if (c < 2) s_ += tmp;
        tmp = __shfl_sync(FULLM, s_, lane + 4);  if (c < 4) s_ += tmp;
        tmp = __shfl_sync(FULLM, s_, lane + 2);  if (c < 2) s_ += tmp;
        tmp = __shfl_sync(FULLM, s_, lane + 1);  if (c < 1) s_ += tmp;
        float se = __shfl_sync(FULLM, s_, g * 10);

        float wgt = __fdividef(e, se);
#pragma unroll
        for (int l = 0; l < L_; l++) acc[l] = fmaf(wgt, f[l], acc[l]);
    }

    // combine the 3 groups (lane i, i+10, i+20 share capsule c=i)
#pragma unroll
    for (int l = 0; l < L_; l++) {
        float a1 = __shfl_sync(FULLM, acc[l], lane + 10);
        float a2 = __shfl_sync(FULLM, acc[l], lane + 20);
        if (lane < 10) acc[l] += a1 + a2;
    }
    if (lane < 10) {
#pragma unroll
        for (int l = 0; l < L_; l++)
            atomicAdd(&g_s[ROUND][b * KDIM + lane * L_ + l], acc[l]);
    }
}

// ---------------------------------------------------------------------------
// Final squash of s2 -> d_out
// ---------------------------------------------------------------------------
__global__ void __launch_bounds__(160) k_out(const float* __restrict__ bias,
                                             float* __restrict__ out) {
    int b = blockIdx.x, t = threadIdx.x;
    out[b * KDIM + t] = squash16(g_s[2][b * KDIM + t] + bias[t]);
}

// ---------------------------------------------------------------------------
extern "C" void kernel_launch(void* const* d_in, const int* in_sizes, int n_in,
                              void* d_out, int out_size) {
    const float* x    = (const float*)d_in[0];   // [128,12,12,32,8] = [B, N, 8]
    const float* W    = (const float*)d_in[1];   // [4608, 8, 160]
    const float* bias = (const float*)d_in[2];   // [10, 16]
    float* out = (float*)d_out;                  // [128, 10, 16]
    (void)in_sizes; (void)n_in; (void)out_size;

    k_zero<<<(3 * SROW + 255) / 256, 256>>>();
    k_u_s0<<<dim3(B_ / 32, N_ / 32), 160>>>(x, W);
    k_route<1><<<dim3(B_, 6), 256>>>(bias);
    k_route<2><<<dim3(B_, 6), 256>>>(bias);
    k_out<<<B_, 160>>>(bias, out);
}

// round 5
// speedup vs baseline: 1.3780x; 1.0318x over previous
#include <cuda_runtime.h>
#include <cuda_fp16.h>
#include <cstdint>

// Problem constants
#define B_   128
#define N_   4608
#define IL_  8
#define C_   10
#define L_   16
#define KDIM 160          // C_*L_
#define SROW (B_*KDIM)    // 20480

// Scratch (allocation-free rule: __device__ globals)
__device__ __half g_uh[(size_t)B_ * N_ * KDIM];   // 188 MB prediction tensor (fp16)
__device__ float  g_s[3][SROW];                   // s accumulators per round

// ---------------------------------------------------------------------------
// Zero the s accumulators (must happen every replay)
// ---------------------------------------------------------------------------
__global__ void k_zero() {
    int i = blockIdx.x * blockDim.x + threadIdx.x;
    if (i < 3 * SROW) ((float*)g_s)[i] = 0.0f;
}

// ---------------------------------------------------------------------------
// K1: u[b,n,k] = sum_j x[b,n,j] * W[n,j,k]  (HFMA2 compute, fp16 store) FUSED
//     with s0[b,k] += 0.1 * sum_n u[b,n,k]
// grid (B/16, N/32), block 160 (thread = k).
// half2 lanes pair over batch: u2 = (u[b], u[b+1]) for fixed k.
// x staged in smem pre-paired: xs2[nj][j][bp] = (x[2bp,nj,j], x[2bp+1,nj,j])
// -> 1 LDS.32 broadcast + 1 HFMA2 per j per 2 outputs.
// ---------------------------------------------------------------------------
__global__ void __launch_bounds__(160) k_u_s0(const float* __restrict__ x,
                                              const float* __restrict__ W) {
    int b0 = blockIdx.x * 16;
    int n0 = blockIdx.y * 32;
    int k = threadIdx.x;
    __shared__ __half2 xs2[32 * IL_ * 8];   // 8 KB, [nj][j][bp]

    // cooperative load + fp16 pack of the x tile
    for (int idx = k; idx < 16 * 32 * IL_; idx += 160) {
        int bi = idx >> 8, r = idx & 255;   // r = nj*8+j, contiguous in gmem
        float val = x[(size_t)(b0 + bi) * (N_ * IL_) + (size_t)n0 * IL_ + r];
        ((__half*)xs2)[r * 16 + bi] = __float2half_rn(val);
    }
    __syncthreads();

    float s0acc[16];
#pragma unroll
    for (int i = 0; i < 16; i++) s0acc[i] = 0.0f;

    for (int nj = 0; nj < 32; nj++) {
        const float* Wn = W + (size_t)(n0 + nj) * (IL_ * KDIM);
        __half2 w2[IL_];
#pragma unroll
        for (int j = 0; j < IL_; j++)
            w2[j] = __half2half2(__float2half_rn(Wn[j * KDIM + k]));
        __half* op = g_uh + ((size_t)b0 * N_ + (n0 + nj)) * KDIM + k;
        const __half2* xp = &xs2[nj * (IL_ * 8)];
#pragma unroll
        for (int bp = 0; bp < 8; bp++) {
            __half2 u2 = __hmul2(xp[0 * 8 + bp], w2[0]);
#pragma unroll
            for (int j = 1; j < IL_; j++)
                u2 = __hfma2(xp[j * 8 + bp], w2[j], u2);
            float2 uf = __half22float2(u2);
            s0acc[2 * bp]     += uf.x;
            s0acc[2 * bp + 1] += uf.y;
            op[(size_t)(2 * bp) * (N_ * KDIM)]     = __low2half(u2);
            op[(size_t)(2 * bp + 1) * (N_ * KDIM)] = __high2half(u2);
        }
    }
#pragma unroll
    for (int bi = 0; bi < 16; bi++)
        atomicAdd(&g_s[0][(b0 + bi) * KDIM + k], 0.1f * s0acc[bi]);
}

// ---------------------------------------------------------------------------
// squash helper applied to one element owned by thread in an aligned 16-group
// ---------------------------------------------------------------------------
__device__ __forceinline__ float squash16(float val) {
    float sq = val * val;
    sq += __shfl_xor_sync(0xffffffffu, sq, 8);
    sq += __shfl_xor_sync(0xffffffffu, sq, 4);
    sq += __shfl_xor_sync(0xffffffffu, sq, 2);
    sq += __shfl_xor_sync(0xffffffffu, sq, 1);
    float nrm = sqrtf(sq);
    return sq / (1.0f + sq) / (nrm + 1e-7f) * val;
}

// ---------------------------------------------------------------------------
// Routing pass (squash fused into the prologue; no b-logit tensor).
// ROUND==1: logit p = u.v0       -> accumulate s1
// ROUND==2: logit p = u.(v0+v1)  -> accumulate s2
// grid (B, 5): chunks of {1024,1024,1024,1024,512} n -> 640 blocks ~ one full
// residency wave (4 blocks/SM x 148). 10-lane groups, 3 n per warp-iteration,
// ragged tail handled by predicate.
// ---------------------------------------------------------------------------
#define FULLM 0xffffffffu
template <int ROUND>
__global__ void __launch_bounds__(256) k_route(const float* __restrict__ bias) {
    int b = blockIdx.x;
    int chunk = blockIdx.y;            // 0..4
    int t = threadIdx.x;

    __shared__ float vs[KDIM];         // v0 (round1) or v0+v1 (round2)
    if (t < KDIM) {
        float bval = bias[t];
        float v0 = squash16(g_s[0][b * KDIM + t] + bval);
        if (ROUND == 1) vs[t] = v0;
        else            vs[t] = v0 + squash16(g_s[1][b * KDIM + t] + bval);
    }
    __syncthreads();

    int warp = t >> 5;
    int lane = t & 31;
    int g = (lane >= 20) ? 2 : (lane >= 10 ? 1 : 0);
    int c = lane - g * 10;
    bool lactive = (lane < 30);

    float vr[L_], acc[L_];
#pragma unroll
    for (int l = 0; l < L_; l++) {
        vr[l] = lactive ? vs[c * L_ + l] : 0.0f;
        acc[l] = 0.0f;
    }

    int npw   = (chunk == 4) ? 64 : 128;           // n per warp
    int iters = (npw + 2) / 3;                     // 22 or 43
    int base_n = chunk * 1024 + warp * npw;
    const __half* ubase = g_uh + ((size_t)b * N_ + base_n) * KDIM + c * L_;

#pragma unroll 2
    for (int it = 0; it < iters; it++) {
        int noff = it * 3 + g;
        bool active = lactive && (noff < npw);
        const __half* up = ubase + (size_t)noff * KDIM;
        uint4 z4 = make_uint4(0u, 0u, 0u, 0u);
        uint4 ua = active ? *(const uint4*)up : z4;
        uint4 ub = active ? *(const uint4*)(up + 8) : z4;
        float f[L_];
        {
            unsigned uu[8] = {ua.x, ua.y, ua.z, ua.w, ub.x, ub.y, ub.z, ub.w};
#pragma unroll
            for (int q = 0; q < 8; q++) {
                float2 fq = __half22float2(*(const __half2*)&uu[q]);
                f[2 * q] = fq.x; f[2 * q + 1] = fq.y;
            }
        }
        float p = 0.0f;
#pragma unroll
        for (int l = 0; l < L_; l++) p = fmaf(f[l], vr[l], p);

        float e = active ? __expf(p) : 0.0f;

        // sum over the 10-lane group (c = 0..9); inactive groups divide 0/eps
        float s_ = e, tmp;
        tmp = __shfl_sync(FULLM, s_, lane + 8);  if (c < 2) s_ += tmp;
        tmp = __shfl_sync(FULLM, s_, lane + 4);  if (c < 4) s_ += tmp;
        tmp = __shfl_sync(FULLM, s_, lane + 2);  if (c < 2) s_ += tmp;
        tmp = __shfl_sync(FULLM, s_, lane + 1);  if (c < 1) s_ += tmp;
        float se = __shfl_sync(FULLM, s_, g * 10) + 1e-30f;

        float wgt = __fdividef(e, se);
#pragma unroll
        for (int l = 0; l < L_; l++) acc[l] = fmaf(wgt, f[l], acc[l]);
    }

    // combine the 3 groups (lane i, i+10, i+20 share capsule c=i)
#pragma unroll
    for (int l = 0; l < L_; l++) {
        float a1 = __shfl_sync(FULLM, acc[l], lane + 10);
        float a2 = __shfl_sync(FULLM, acc[l], lane + 20);
        if (lane < 10) acc[l] += a1 + a2;
    }
    if (lane < 10) {
#pragma unroll
        for (int l = 0; l < L_; l++)
            atomicAdd(&g_s[ROUND][b * KDIM + lane * L_ + l], acc[l]);
    }
}

// ---------------------------------------------------------------------------
// Final squash of s2 -> d_out
// ---------------------------------------------------------------------------
__global__ void __launch_bounds__(160) k_out(const float* __restrict__ bias,
                                             float* __restrict__ out) {
    int b = blockIdx.x, t = threadIdx.x;
    out[b * KDIM + t] = squash16(g_s[2][b * KDIM + t] + bias[t]);
}

// ---------------------------------------------------------------------------
extern "C" void kernel_launch(void* const* d_in, const int* in_sizes, int n_in,
                              void* d_out, int out_size) {
    const float* x    = (const float*)d_in[0];   // [128,12,12,32,8] = [B, N, 8]
    const float* W    = (const float*)d_in[1];   // [4608, 8, 160]
    const float* bias = (const float*)d_in[2];   // [10, 16]
    float* out = (float*)d_out;                  // [128, 10, 16]
    (void)in_sizes; (void)n_in; (void)out_size;

    k_zero<<<(3 * SROW + 255) / 256, 256>>>();
    k_u_s0<<<dim3(B_ / 16, N_ / 32), 160>>>(x, W);
    k_route<1><<<dim3(B_, 5), 256>>>(bias);
    k_route<2><<<dim3(B_, 5), 256>>>(bias);
    k_out<<<B_, 160>>>(bias, out);
}

// round 6
// speedup vs baseline: 1.9277x; 1.3989x over previous
#include <cuda_runtime.h>
#include <cuda_fp16.h>
#include <cstdint>

// Problem constants
#define B_   128
#define N_   4608
#define IL_  8
#define C_   10
#define L_   16
#define KDIM 160          // C_*L_
#define SROW (B_*KDIM)    // 20480

typedef unsigned long long u64t;

// packed f32x2 helpers (sm_103a FFMA2 path — PTX only, ptxas won't auto-fuse)
__device__ __forceinline__ u64t pk2(float lo, float hi) {
    u64t r; asm("mov.b64 %0,{%1,%2};" : "=l"(r) : "f"(lo), "f"(hi)); return r;
}
__device__ __forceinline__ void upk2(u64t v, float& lo, float& hi) {
    asm("mov.b64 {%0,%1},%2;" : "=f"(lo), "=f"(hi) : "l"(v));
}
__device__ __forceinline__ u64t ffma2(u64t a, u64t b, u64t c) {
    u64t d; asm("fma.rn.f32x2 %0,%1,%2,%3;" : "=l"(d) : "l"(a), "l"(b), "l"(c));
    return d;
}
__device__ __forceinline__ u64t fmul2(u64t a, u64t b) {
    u64t d; asm("mul.rn.f32x2 %0,%1,%2;" : "=l"(d) : "l"(a), "l"(b)); return d;
}
__device__ __forceinline__ u64t fadd2(u64t a, u64t b) {
    u64t d; asm("add.rn.f32x2 %0,%1,%2;" : "=l"(d) : "l"(a), "l"(b)); return d;
}

// Scratch (allocation-free rule: __device__ globals)
__device__ __half g_uh[(size_t)B_ * N_ * KDIM];   // 188 MB prediction tensor (fp16)
__device__ float  g_s[3][SROW];                   // s accumulators per round

// ---------------------------------------------------------------------------
// Zero the s accumulators (must happen every replay)
// ---------------------------------------------------------------------------
__global__ void k_zero() {
    int i = blockIdx.x * blockDim.x + threadIdx.x;
    if (i < 3 * SROW) ((float*)g_s)[i] = 0.0f;
}

// ---------------------------------------------------------------------------
// K1: u[b,n,k] = sum_j x[b,n,j] * W[n,j,k]  (fp32 via packed FFMA2, fp16
//     store) FUSED with s0[b,k] += 0.1 * sum_n u[b,n,k].
// grid (B/16, N/32), block 160 (thread = k).
// f32x2 lanes pair over batch: u2 = (u[2bp], u[2bp+1]) for fixed (n,k).
// x tile in smem as packed pairs, layout [nj][bp][j] (j contiguous for the
// dot), read via 8-byte broadcast LDS. Full fp32 accumulation -> u rounded
// to fp16 exactly once.
// ---------------------------------------------------------------------------
__global__ void __launch_bounds__(160) k_u_s0(const float* __restrict__ x,
                                              const float* __restrict__ W) {
    int b0 = blockIdx.x * 16;
    int n0 = blockIdx.y * 32;
    int k = threadIdx.x;
    __shared__ u64t xs2[32 * 8 * 8];   // 16 KB, [nj][bp][j], pair over batch

    for (int idx = k; idx < 16 * 32 * IL_; idx += 160) {
        int bi = idx >> 8, r = idx & 255;        // r = nj*8 + j (contig in gmem)
        int nj = r >> 3, j = r & 7;
        float val = x[(size_t)(b0 + bi) * (N_ * IL_) + (size_t)n0 * IL_ + r];
        ((float*)xs2)[((nj * 8 + (bi >> 1)) * 8 + j) * 2 + (bi & 1)] = val;
    }
    __syncthreads();

    u64t s0a[8];
#pragma unroll
    for (int i = 0; i < 8; i++) s0a[i] = pk2(0.f, 0.f);

    for (int nj = 0; nj < 32; nj++) {
        const float* Wn = W + (size_t)(n0 + nj) * (IL_ * KDIM);
        u64t w2[IL_];
#pragma unroll
        for (int j = 0; j < IL_; j++) {
            float w = Wn[j * KDIM + k];
            w2[j] = pk2(w, w);
        }
        __half* op = g_uh + ((size_t)b0 * N_ + (n0 + nj)) * KDIM + k;
        const u64t* xp = &xs2[nj * 64];
#pragma unroll
        for (int bp = 0; bp < 8; bp++) {
            u64t u2 = fmul2(xp[bp * 8], w2[0]);
#pragma unroll
            for (int j = 1; j < IL_; j++)
                u2 = ffma2(xp[bp * 8 + j], w2[j], u2);
            s0a[bp] = fadd2(s0a[bp], u2);
            float f0, f1; upk2(u2, f0, f1);
            op[(size_t)(2 * bp) * (N_ * KDIM)]     = __float2half_rn(f0);
            op[(size_t)(2 * bp + 1) * (N_ * KDIM)] = __float2half_rn(f1);
        }
    }
#pragma unroll
    for (int bp = 0; bp < 8; bp++) {
        float f0, f1; upk2(s0a[bp], f0, f1);
        atomicAdd(&g_s[0][(b0 + 2 * bp) * KDIM + k],     0.1f * f0);
        atomicAdd(&g_s[0][(b0 + 2 * bp + 1) * KDIM + k], 0.1f * f1);
    }
}

// ---------------------------------------------------------------------------
// squash helper applied to one element owned by thread in an aligned 16-group
// ---------------------------------------------------------------------------
__device__ __forceinline__ float squash16(float val) {
    float sq = val * val;
    sq += __shfl_xor_sync(0xffffffffu, sq, 8);
    sq += __shfl_xor_sync(0xffffffffu, sq, 4);
    sq += __shfl_xor_sync(0xffffffffu, sq, 2);
    sq += __shfl_xor_sync(0xffffffffu, sq, 1);
    float nrm = sqrtf(sq);
    return sq / (1.0f + sq) / (nrm + 1e-7f) * val;
}

// ---------------------------------------------------------------------------
// Routing pass (squash fused into the prologue; no b-logit tensor).
// ROUND==1: logit p = u.v0       -> accumulate s1
// ROUND==2: logit p = u.(v0+v1)  -> accumulate s2
// grid (B, 5): n-chunks {960,960,960,960,768}; per-warp n = 120/96, both
// divisible by 3 -> exact trip counts, no tail predicate. 10-lane groups,
// 3 n per warp-iteration. Dot in half2 (8 HFMA2); softmax sum via 4
// predicated shfl steps; acc in fp32.
// ---------------------------------------------------------------------------
#define FULLM 0xffffffffu
template <int ROUND>
__global__ void __launch_bounds__(256, 5) k_route(const float* __restrict__ bias) {
    int b = blockIdx.x;
    int chunk = blockIdx.y;            // 0..4
    int t = threadIdx.x;

    __shared__ float vs[KDIM];         // v0 (round1) or v0+v1 (round2)
    if (t < KDIM) {
        float bval = bias[t];
        float v0 = squash16(g_s[0][b * KDIM + t] + bval);
        if (ROUND == 1) vs[t] = v0;
        else            vs[t] = v0 + squash16(g_s[1][b * KDIM + t] + bval);
    }
    __syncthreads();

    int warp = t >> 5;
    int lane = t & 31;
    int g = (lane >= 20) ? 2 : (lane >= 10 ? 1 : 0);
    int c = lane - g * 10;
    bool active = (lane < 30);

    __half2 vr2[8];
    float acc[L_];
#pragma unroll
    for (int q = 0; q < 8; q++)
        vr2[q] = active ? __floats2half2_rn(vs[c * L_ + 2 * q],
                                            vs[c * L_ + 2 * q + 1])
                        : __floats2half2_rn(0.f, 0.f);
#pragma unroll
    for (int l = 0; l < L_; l++) acc[l] = 0.0f;

    int npw   = (chunk == 4) ? 96 : 120;   // n per warp, divisible by 3
    int iters = npw / 3;                   // 32 or 40
    int base_n = chunk * 960 + warp * npw;
    const __half* ubase = g_uh + ((size_t)b * N_ + base_n) * KDIM + c * L_;

#pragma unroll 4
    for (int it = 0; it < iters; it++) {
        const __half* up = ubase + (size_t)(it * 3 + g) * KDIM;
        uint4 z4 = make_uint4(0u, 0u, 0u, 0u);
        uint4 ua = active ? *(const uint4*)up : z4;
        uint4 ub = active ? *(const uint4*)(up + 8) : z4;
        __half2 u2[8];
        u2[0] = *(__half2*)&ua.x; u2[1] = *(__half2*)&ua.y;
        u2[2] = *(__half2*)&ua.z; u2[3] = *(__half2*)&ua.w;
        u2[4] = *(__half2*)&ub.x; u2[5] = *(__half2*)&ub.y;
        u2[6] = *(__half2*)&ub.z; u2[7] = *(__half2*)&ub.w;

        // logit: half2 dot (values bounded ~2 -> fp16-safe)
        __half2 p2 = __hmul2(u2[0], vr2[0]);
#pragma unroll
        for (int q = 1; q < 8; q++) p2 = __hfma2(u2[q], vr2[q], p2);
        float p = __low2float(p2) + __high2float(p2);

        float e = active ? __expf(p) : 0.0f;

        // sum over the 10-lane group (c = 0..9)
        float s_ = e, tmp;
        tmp = __shfl_sync(FULLM, s_, lane + 8);  if (c < 2) s_ += tmp;
        tmp = __shfl_sync(FULLM, s_, lane + 4);  if (c < 4) s_ += tmp;
        tmp = __shfl_sync(FULLM, s_, lane + 2);  if (c < 2) s_ += tmp;
        tmp = __shfl_sync(FULLM, s_, lane + 1);  if (c < 1) s_ += tmp;
        float se = __shfl_sync(FULLM, s_, g * 10) + 1e-30f;

        float wgt = __fdividef(e, se);
#pragma unroll
        for (int q = 0; q < 8; q++) {
            float2 fq = __half22float2(u2[q]);
            acc[2 * q]     = fmaf(wgt, fq.x, acc[2 * q]);
            acc[2 * q + 1] = fmaf(wgt, fq.y, acc[2 * q + 1]);
        }
    }

    // combine the 3 groups (lane i, i+10, i+20 share capsule c=i)
#pragma unroll
    for (int l = 0; l < L_; l++) {
        float a1 = __shfl_sync(FULLM, acc[l], lane + 10);
        float a2 = __shfl_sync(FULLM, acc[l], lane + 20);
        if (lane < 10) acc[l] += a1 + a2;
    }
    if (lane < 10) {
#pragma unroll
        for (int l = 0; l < L_; l++)
            atomicAdd(&g_s[ROUND][b * KDIM + lane * L_ + l], acc[l]);
    }
}

// ---------------------------------------------------------------------------
// Final squash of s2 -> d_out
// ---------------------------------------------------------------------------
__global__ void __launch_bounds__(160) k_out(const float* __restrict__ bias,
                                             float* __restrict__ out) {
    int b = blockIdx.x, t = threadIdx.x;
    out[b * KDIM + t] = squash16(g_s[2][b * KDIM + t] + bias[t]);
}

// ---------------------------------------------------------------------------
extern "C" void kernel_launch(void* const* d_in, const int* in_sizes, int n_in,
                              void* d_out, int out_size) {
    const float* x    = (const float*)d_in[0];   // [128,12,12,32,8] = [B, N, 8]
    const float* W    = (const float*)d_in[1];   // [4608, 8, 160]
    const float* bias = (const float*)d_in[2];   // [10, 16]
    float* out = (float*)d_out;                  // [128, 10, 16]
    (void)in_sizes; (void)n_in; (void)out_size;

    k_zero<<<(3 * SROW + 255) / 256, 256>>>();
    k_u_s0<<<dim3(B_ / 16, N_ / 32), 160>>>(x, W);
    k_route<1><<<dim3(B_, 5), 256>>>(bias);
    k_route<2><<<dim3(B_, 5), 256>>>(bias);
    k_out<<<B_, 160>>>(bias, out);
}